// round 5
// baseline (speedup 1.0000x reference)
#include <cuda_runtime.h>
#include <cuda_bf16.h>

// Elementwise clip: out = min(max(x, lo), hi)
// 33,554,432 fp32 = 8,388,608 float4s.
// Persistent single-wave grid: 1184 blocks (148 SMs x 8 CTAs) x 256 threads,
// grid-stride with x4-batched streaming LDG.128/STG.128. No wave transitions,
// no tail-wave imbalance; tail handled per-thread (<=3 extra float4s).

__global__ __launch_bounds__(256) void clip_kernel_persist(
    const float4* __restrict__ x,
    const float* __restrict__ clamp_params,
    float4* __restrict__ out,
    int n4)
{
    const float lo = clamp_params[0];
    const float hi = clamp_params[1];

    const int stride = gridDim.x * blockDim.x;       // total threads
    int i = blockIdx.x * blockDim.x + threadIdx.x;

    // Main loop: 4 independent front-batched loads per iteration.
    for (; i + 3 * stride < n4; i += 4 * stride) {
        float4 v0 = __ldcs(&x[i]);
        float4 v1 = __ldcs(&x[i + stride]);
        float4 v2 = __ldcs(&x[i + 2 * stride]);
        float4 v3 = __ldcs(&x[i + 3 * stride]);

        v0.x = fminf(fmaxf(v0.x, lo), hi); v0.y = fminf(fmaxf(v0.y, lo), hi);
        v0.z = fminf(fmaxf(v0.z, lo), hi); v0.w = fminf(fmaxf(v0.w, lo), hi);
        v1.x = fminf(fmaxf(v1.x, lo), hi); v1.y = fminf(fmaxf(v1.y, lo), hi);
        v1.z = fminf(fmaxf(v1.z, lo), hi); v1.w = fminf(fmaxf(v1.w, lo), hi);
        v2.x = fminf(fmaxf(v2.x, lo), hi); v2.y = fminf(fmaxf(v2.y, lo), hi);
        v2.z = fminf(fmaxf(v2.z, lo), hi); v2.w = fminf(fmaxf(v2.w, lo), hi);
        v3.x = fminf(fmaxf(v3.x, lo), hi); v3.y = fminf(fmaxf(v3.y, lo), hi);
        v3.z = fminf(fmaxf(v3.z, lo), hi); v3.w = fminf(fmaxf(v3.w, lo), hi);

        __stcs(&out[i],              v0);
        __stcs(&out[i + stride],     v1);
        __stcs(&out[i + 2 * stride], v2);
        __stcs(&out[i + 3 * stride], v3);
    }

    // Tail: at most 3 float4s per thread.
    for (; i < n4; i += stride) {
        float4 v = __ldcs(&x[i]);
        v.x = fminf(fmaxf(v.x, lo), hi);
        v.y = fminf(fmaxf(v.y, lo), hi);
        v.z = fminf(fmaxf(v.z, lo), hi);
        v.w = fminf(fmaxf(v.w, lo), hi);
        __stcs(&out[i], v);
    }
}

// Scalar fallback for sizes not divisible by 4.
__global__ __launch_bounds__(256) void clip_kernel_generic(
    const float* __restrict__ x,
    const float* __restrict__ clamp_params,
    float* __restrict__ out,
    int n)
{
    const float lo = clamp_params[0];
    const float hi = clamp_params[1];
    for (int i = blockIdx.x * blockDim.x + threadIdx.x; i < n;
         i += gridDim.x * blockDim.x)
        out[i] = fminf(fmaxf(__ldcs(&x[i]), lo), hi);
}

extern "C" void kernel_launch(void* const* d_in, const int* in_sizes, int n_in,
                              void* d_out, int out_size)
{
    const float* x = (const float*)d_in[0];
    const float* clamp_params = (const float*)d_in[1];
    float* out = (float*)d_out;

    int n = out_size;              // 33,554,432
    const int threads = 256;
    const int blocks = 148 * 8;    // one full wave: 1184 CTAs

    if ((n & 3) == 0) {
        int n4 = n >> 2;           // 8,388,608
        clip_kernel_persist<<<blocks, threads>>>(
            (const float4*)x, clamp_params, (float4*)out, n4);
    } else {
        clip_kernel_generic<<<blocks, threads>>>(x, clamp_params, out, n);
    }
}

// round 6
// speedup vs baseline: 1.2412x; 1.2412x over previous
#include <cuda_runtime.h>
#include <cuda_bf16.h>

// Elementwise clip: out = min(max(x, lo), hi)
// 33,554,432 fp32 = 4,194,304 float8s = 8192 blocks x 256 threads x 2 (exact).
// sm_100+ 256-bit global accesses (LDG.E.256 / STG.E.256): each warp load covers
// a dense 1KB burst -> fewer L1tex wavefronts, wider DRAM bursts.
// Geometry identical to the proven best (64B/thread, one-shot CTAs).

__device__ __forceinline__ void ld256_cs(const float* p, float4& a, float4& b)
{
    asm volatile(
        "ld.global.cs.v8.f32 {%0,%1,%2,%3,%4,%5,%6,%7}, [%8];"
        : "=f"(a.x), "=f"(a.y), "=f"(a.z), "=f"(a.w),
          "=f"(b.x), "=f"(b.y), "=f"(b.z), "=f"(b.w)
        : "l"(p));
}

__device__ __forceinline__ void st256_cs(float* p, const float4& a, const float4& b)
{
    asm volatile(
        "st.global.cs.v8.f32 [%0], {%1,%2,%3,%4,%5,%6,%7,%8};"
        :: "l"(p),
           "f"(a.x), "f"(a.y), "f"(a.z), "f"(a.w),
           "f"(b.x), "f"(b.y), "f"(b.z), "f"(b.w)
        : "memory");
}

__device__ __forceinline__ float4 clip4(float4 v, float lo, float hi)
{
    v.x = fminf(fmaxf(v.x, lo), hi);
    v.y = fminf(fmaxf(v.y, lo), hi);
    v.z = fminf(fmaxf(v.z, lo), hi);
    v.w = fminf(fmaxf(v.w, lo), hi);
    return v;
}

__global__ __launch_bounds__(256) void clip_kernel_v8x2_exact(
    const float* __restrict__ x,
    const float* __restrict__ clamp_params,
    float* __restrict__ out)
{
    const float lo = clamp_params[0];
    const float hi = clamp_params[1];

    // Index in float8 units; 2 accesses per thread, stride 256 between them.
    long long t = (long long)blockIdx.x * (256 * 2) + threadIdx.x;

    float4 a0, b0, a1, b1;
    ld256_cs(x + t * 8, a0, b0);
    ld256_cs(x + (t + 256) * 8, a1, b1);

    a0 = clip4(a0, lo, hi);  b0 = clip4(b0, lo, hi);
    a1 = clip4(a1, lo, hi);  b1 = clip4(b1, lo, hi);

    st256_cs(out + t * 8, a0, b0);
    st256_cs(out + (t + 256) * 8, a1, b1);
}

// Generic fallback (any size).
__global__ __launch_bounds__(256) void clip_kernel_generic(
    const float* __restrict__ x,
    const float* __restrict__ clamp_params,
    float* __restrict__ out,
    int n)
{
    const float lo = clamp_params[0];
    const float hi = clamp_params[1];
    for (int i = blockIdx.x * blockDim.x + threadIdx.x; i < n;
         i += gridDim.x * blockDim.x)
        out[i] = fminf(fmaxf(__ldcs(&x[i]), lo), hi);
}

extern "C" void kernel_launch(void* const* d_in, const int* in_sizes, int n_in,
                              void* d_out, int out_size)
{
    const float* x = (const float*)d_in[0];
    const float* clamp_params = (const float*)d_in[1];
    float* out = (float*)d_out;

    int n = out_size;                       // 33,554,432
    const int threads = 256;
    const int chunk = threads * 2 * 8;      // floats per block: 4096

    if ((n % chunk) == 0) {
        int blocks = n / chunk;             // 8192
        clip_kernel_v8x2_exact<<<blocks, threads>>>(x, clamp_params, out);
    } else {
        int blocks = (n + threads - 1) / threads;
        if (blocks > 65535 * 16) blocks = 65535 * 16;
        clip_kernel_generic<<<blocks, threads>>>(x, clamp_params, out, n);
    }
}